// round 13
// baseline (speedup 1.0000x reference)
#include <cuda_runtime.h>
#include <cuda_bf16.h>
#include <cstdint>

#define N_NODES 20000
#define E_EDGES 640000
#define P_DIM   12
#define H_DIM   128
#define O_DIM   12
#define DEG_BLOCKS  (E_EDGES / 4 / 256)           // 625
#define DINV_BLOCKS ((N_NODES + 255) / 256)       // 79
#define EDGES_PER_WARP 10                          // 3 lanes per edge, 2 idle lanes
#define DEG_C   10                                 // poly degree 9 -> 10 coeffs
#define M_FIT   16                                 // Chebyshev nodes
#define A_FIT   8.0f                               // fit domain [-A, A]

// ---------------- scratch (no dynamic allocation; zero-initialized at load) ----------------
// INVARIANT: g_deg and g_agg are all-zero at entry of every kernel_launch call
// (zeroed at module load, re-zeroed inside each launch after consumption).
__device__ float g_deg [N_NODES];
__device__ float g_dinv[N_NODES];
__device__ float g_xs  [N_NODES * P_DIM];   // dinv[n] * x[n,:]
__device__ float g_agg [N_NODES * P_DIM];   // un-dst-normalized aggregate
__device__ float g_coef[DEG_C * H_DIM];     // monomial coeffs of g_k(t), t = a/A_FIT
__device__ float g_probs[P_DIM];

// ---------------- deg atomics (4 edges/thread) + gate-fold + Chebyshev fit ----------------
// blocks [0, DEG_BLOCKS) : degree accumulation
// block DEG_BLOCKS       : fold BOTH gates (z in threads 0-127, h in 128-255), then
//                          per-k degree-9 Chebyshev fit of
//                          g_k(a) = (0.5 - 0.5*tanh(0.5*(az*a+bz))) * tanh(ah*a+bh)
__global__ void __launch_bounds__(256) k_deg_fold(
        const int* __restrict__ ei,    const float* __restrict__ ew,
        const float* __restrict__ cwz, const float* __restrict__ cbz,
        const float* __restrict__ Wz,  const float* __restrict__ lbz,
        const float* __restrict__ cwh, const float* __restrict__ cbh,
        const float* __restrict__ Wh,  const float* __restrict__ lbh) {
    int b = blockIdx.x;
    int tid = threadIdx.x;
    if (b < DEG_BLOCKS) {
        int e4 = (b * 256 + tid) * 4;
        int4   d = *(const int4*)  (ei + E_EDGES + e4);
        float4 w = *(const float4*)(ew + e4);
        atomicAdd(&g_deg[d.x], w.x);
        atomicAdd(&g_deg[d.y], w.y);
        atomicAdd(&g_deg[d.z], w.z);
        atomicAdd(&g_deg[d.w], w.w);
        return;
    }
    // ---- fold ----
    __shared__ float saz[H_DIM], sbz[H_DIM], sah[H_DIM], sbh[H_DIM];
    int k = tid & 127;
    bool hgate = tid >= 128;
    const float* cw = hgate ? cwh : cwz;
    const float* cb = hgate ? cbh : cbz;
    const float* W  = hgate ? Wh  : Wz;
    const float* lb = hgate ? lbh : lbz;
    float pa = 0.f, pb = 0.f;
#pragma unroll 8
    for (int h = 0; h < H_DIM; h++) {
        float w = W[h * H_DIM + k];
        pa = fmaf(cw[h], w, pa);
        pb = fmaf(cb[h], w, pb);
    }
    pb += lb[k];
    if (hgate) { sah[k] = pa; sbh[k] = pb; }
    else       { saz[k] = pa; sbz[k] = pb; }
    __syncthreads();
    if (tid >= 128) return;
    // ---- Chebyshev projection (deg 9, 16 nodes, exact tanhf) ----
    float azf = saz[k], bzf = sbz[k], ahf = sah[k], bhf = sbh[k];
    float c[DEG_C];
#pragma unroll
    for (int m = 0; m < DEG_C; m++) c[m] = 0.f;
    for (int i = 0; i < M_FIT; i++) {
        float x = cospif((2 * i + 1) / (2.0f * M_FIT));   // cos(pi*(i+0.5)/M)
        float a = A_FIT * x;
        float gz = 0.5f - 0.5f * tanhf(0.5f * fmaf(azf, a, bzf));
        float gh = tanhf(fmaf(ahf, a, bhf));
        float g  = gz * gh;
        float T0 = 1.0f, T1 = x;
        c[0] += g;
        c[1] += g * x;
#pragma unroll
        for (int m = 2; m < DEG_C; m++) {
            float T = 2.0f * x * T1 - T0;
            c[m] += g * T;
            T0 = T1; T1 = T;
        }
    }
    c[0] *= 1.0f / M_FIT;
#pragma unroll
    for (int m = 1; m < DEG_C; m++) c[m] *= 2.0f / M_FIT;
    // ---- Chebyshev -> monomial ----
    float mono[DEG_C], Tp[DEG_C], Tc[DEG_C];
#pragma unroll
    for (int j = 0; j < DEG_C; j++) { Tp[j] = 0.f; Tc[j] = 0.f; mono[j] = 0.f; }
    Tp[0] = 1.0f; Tc[1] = 1.0f;
#pragma unroll
    for (int j = 0; j < DEG_C; j++) mono[j] = c[0] * Tp[j] + c[1] * Tc[j];
#pragma unroll
    for (int m = 2; m < DEG_C; m++) {
        float Tn[DEG_C];
        Tn[0] = -Tp[0];
#pragma unroll
        for (int j = 1; j < DEG_C; j++) Tn[j] = 2.0f * Tc[j - 1] - Tp[j];
#pragma unroll
        for (int j = 0; j < DEG_C; j++) mono[j] += c[m] * Tn[j];
#pragma unroll
        for (int j = 0; j < DEG_C; j++) { Tp[j] = Tc[j]; Tc[j] = Tn[j]; }
    }
#pragma unroll
    for (int j = 0; j < DEG_C; j++) g_coef[j * H_DIM + k] = mono[j];
}

// ---------------- dinv(+deg reset) + xs prescale + softmax ----------------
__global__ void __launch_bounds__(256) k_dinv(const float* __restrict__ x,
                                              const float* __restrict__ att) {
    __shared__ float s_dinv[256];
    int tid = threadIdx.x;
    int n0 = blockIdx.x * 256;
    int n  = n0 + tid;
    float dv = 0.0f;
    if (n < N_NODES) {
        float d = g_deg[n] + 1.0f;       // self-loop weight folded here
        dv = rsqrtf(d);                  // d >= 1 > 0 always
        g_dinv[n] = dv;
        g_deg[n]  = 0.0f;                // reset for next launch (replay-safe)
    }
    s_dinv[tid] = dv;
    __syncthreads();
    int base  = n0 * P_DIM;
    int count = min(256, N_NODES - n0) * P_DIM;
    for (int j = tid; j < count; j += 256) {
        g_xs[base + j] = s_dinv[j / P_DIM] * x[base + j];
    }
    if (blockIdx.x == 0 && tid == 0) {
        float m = -1e30f;
        for (int p = 0; p < P_DIM; p++) m = fmaxf(m, att[p]);
        float ex[P_DIM]; float s = 0.f;
        for (int p = 0; p < P_DIM; p++) { ex[p] = __expf(att[p] - m); s += ex[p]; }
        float inv = 1.0f / s;
        for (int p = 0; p < P_DIM; p++) g_probs[p] = ex[p] * inv;
    }
}

// ---------------- edge scatter: 3 lanes per edge -> min sector count ----------------
__device__ __forceinline__ void red_add_v4(float* addr, float4 v) {
    asm volatile("red.global.add.v4.f32 [%0], {%1, %2, %3, %4};"
                 :: "l"(addr), "f"(v.x), "f"(v.y), "f"(v.z), "f"(v.w)
                 : "memory");
}

__global__ void __launch_bounds__(256) k_edge(const int* __restrict__ ei,
                                              const float* __restrict__ ew) {
    int warp_g = (blockIdx.x * blockDim.x + threadIdx.x) >> 5;
    int lane   = threadIdx.x & 31;
    if (lane >= 3 * EDGES_PER_WARP) return;          // 2 idle lanes per warp
    int el = lane / 3;                                // edge-in-warp 0..9
    int j  = lane - el * 3;                           // quarter index 0..2
    int e  = warp_g * EDGES_PER_WARP + el;
    if (e >= E_EDGES) return;
    int   s = __ldg(ei + e);
    int   d = __ldg(ei + E_EDGES + e);
    float w = __ldg(ew + e);
    float4 v = *(const float4*)(g_xs + (size_t)s * P_DIM + 4 * j);
    v.x *= w; v.y *= w; v.z *= w; v.w *= w;
    red_add_v4(g_agg + (size_t)d * P_DIM + 4 * j, v);
}

// ---------------- node kernel: moment factorization (no transcendental mainloop) -------
__global__ void __launch_bounds__(256) k_node(const float* __restrict__ wout,
                                              const float* __restrict__ bout,
                                              float* __restrict__ out) {
    __shared__ float s_woutT[O_DIM * H_DIM];
    __shared__ float s_coef [DEG_C * H_DIM];
    __shared__ float s_probs[P_DIM], s_bout[O_DIM];

    int tid = threadIdx.x;
    for (int i = tid; i < H_DIM * O_DIM; i += 256) {
        int k = i / O_DIM, o = i % O_DIM;
        s_woutT[o * H_DIM + k] = wout[i];       // transpose -> conflict-free LDS
    }
    for (int i = tid; i < DEG_C * H_DIM; i += 256) s_coef[i] = g_coef[i];
    if (tid < P_DIM) s_probs[tid] = g_probs[tid];
    if (tid < O_DIM) s_bout[tid]  = bout[tid];
    __syncthreads();

    int warp = tid >> 5, lane = tid & 31;
    int n = blockIdx.x * 8 + warp;
    if (n >= N_NODES) return;

    float dv = g_dinv[n];
    float4*       ar  = (float4*)(g_agg + (size_t)n * P_DIM);
    const float4* xsr = (const float4*)(g_xs + (size_t)n * P_DIM);
    float a[P_DIM];
#pragma unroll
    for (int j = 0; j < 3; j++) {
        float4 av = ar[j];
        float4 xv = xsr[j];
        a[4*j + 0] = dv * (av.x + xv.x);
        a[4*j + 1] = dv * (av.y + xv.y);
        a[4*j + 2] = dv * (av.z + xv.z);
        a[4*j + 3] = dv * (av.w + xv.w);
    }
    // reset agg row for next launch (after all lanes have loaded it)
    if (lane < 3) ar[lane] = make_float4(0.f, 0.f, 0.f, 0.f);

    // moments m_j = sum_p w_p * t_p^j, t = clamp(a/A, -1, 1)
    const float invA = 1.0f / A_FIT;
    float m[DEG_C];
#pragma unroll
    for (int j = 0; j < DEG_C; j++) m[j] = 0.f;
#pragma unroll
    for (int p = 0; p < P_DIM; p++) {
        float t  = fminf(fmaxf(a[p] * invA, -1.0f), 1.0f);
        float wp = s_probs[p];
        m[0] += wp;
        float tj = t;
#pragma unroll
        for (int j = 1; j < DEG_C; j++) {
            m[j] = fmaf(wp, tj, m[j]);
            tj *= t;
        }
    }

    // h_k = sum_j coef[j][k] * m_j   for k = lane + 32q
    float hacc[4] = {0.f, 0.f, 0.f, 0.f};
#pragma unroll
    for (int j = 0; j < DEG_C; j++) {
        float mj = m[j];
#pragma unroll
        for (int q = 0; q < 4; q++)
            hacc[q] = fmaf(mj, s_coef[j * H_DIM + lane + 32 * q], hacc[q]);
    }

    // elu + out matvec (O=12)
    float o_acc[O_DIM];
#pragma unroll
    for (int o = 0; o < O_DIM; o++) o_acc[o] = 0.f;
#pragma unroll
    for (int q = 0; q < 4; q++) {
        float hk = hacc[q];
        hk = (hk > 0.f) ? hk : (__expf(hk) - 1.0f);
        int k = lane + 32 * q;
#pragma unroll
        for (int o = 0; o < O_DIM; o++)
            o_acc[o] = fmaf(hk, s_woutT[o * H_DIM + k], o_acc[o]);
    }

    // split-ownership butterfly: 18 SHFLs instead of 60.
    float v6[6];
    bool lo16 = (lane & 16) == 0;
#pragma unroll
    for (int t = 0; t < 6; t++) {
        float send = lo16 ? o_acc[t + 6] : o_acc[t];
        float recv = __shfl_xor_sync(0xffffffffu, send, 16);
        v6[t] = (lo16 ? o_acc[t] : o_acc[t + 6]) + recv;
    }
    float v3[3];
    bool lo8 = (lane & 8) == 0;
#pragma unroll
    for (int t = 0; t < 3; t++) {
        float send = lo8 ? v6[t + 3] : v6[t];
        float recv = __shfl_xor_sync(0xffffffffu, send, 8);
        v3[t] = (lo8 ? v6[t] : v6[t + 3]) + recv;
    }
#pragma unroll
    for (int off = 4; off > 0; off >>= 1) {
#pragma unroll
        for (int t = 0; t < 3; t++)
            v3[t] += __shfl_xor_sync(0xffffffffu, v3[t], off);
    }
    int r = lane & 7;
    if (r < 3) {
        int o = 3 * (lane >> 3) + r;
        out[(size_t)n * O_DIM + o] = v3[r] + s_bout[o];
    }
}

// ---------------- launch ----------------
extern "C" void kernel_launch(void* const* d_in, const int* in_sizes, int n_in,
                              void* d_out, int out_size) {
    const float* x    = (const float*)d_in[0];
    const int*   ei   = (const int*)  d_in[1];
    const float* ew   = (const float*)d_in[2];
    const float* att  = (const float*)d_in[3];
    const float* cwz  = (const float*)d_in[4];
    const float* cbz  = (const float*)d_in[5];
    const float* Wz   = (const float*)d_in[6];
    const float* lbz  = (const float*)d_in[7];
    // r-gate inputs (d_in[8..11]) are mathematically dead: H=0 => R unused
    const float* cwh  = (const float*)d_in[12];
    const float* cbh  = (const float*)d_in[13];
    const float* Wh   = (const float*)d_in[14];
    const float* lbh  = (const float*)d_in[15];
    const float* wout = (const float*)d_in[16];
    const float* bout = (const float*)d_in[17];
    float* out = (float*)d_out;

    k_deg_fold<<<DEG_BLOCKS + 1, 256>>>(ei, ew, cwz, cbz, Wz, lbz,
                                        cwh, cbh, Wh, lbh);
    k_dinv<<<DINV_BLOCKS, 256>>>(x, att);
    int edge_warps  = (E_EDGES + EDGES_PER_WARP - 1) / EDGES_PER_WARP;   // 64000
    int edge_blocks = (edge_warps + 7) / 8;                               // 8000
    k_edge<<<edge_blocks, 256>>>(ei, ew);
    k_node<<<N_NODES / 8, 256>>>(wout, bout, out);
}

// round 14
// speedup vs baseline: 1.2056x; 1.2056x over previous
#include <cuda_runtime.h>
#include <cuda_bf16.h>
#include <cstdint>

#define N_NODES 20000
#define E_EDGES 640000
#define P_DIM   12
#define H_DIM   128
#define O_DIM   12
#define DEG_BLOCKS  (E_EDGES / 4 / 256)           // 625
#define DINV_BLOCKS ((N_NODES + 255) / 256)       // 79
#define EDGES_PER_WARP 10                          // 3 lanes per edge, 2 idle lanes
#define DEG_C   10                                 // poly degree 9 -> 10 coeffs
#define M_FIT   16                                 // Chebyshev nodes
#define A_FIT   8.0f                               // fit domain [-A, A]
#define NB      16                                 // nodes per k_node block

// ---------------- scratch (no dynamic allocation; zero-initialized at load) ----------------
// INVARIANT: g_deg and g_agg are all-zero at entry of every kernel_launch call
// (zeroed at module load, re-zeroed inside each launch after consumption).
__device__ float g_deg [N_NODES];
__device__ float g_dinv[N_NODES];
__device__ float g_xs  [N_NODES * P_DIM];   // dinv[n] * x[n,:]
__device__ float g_agg [N_NODES * P_DIM];   // un-dst-normalized aggregate
__device__ float g_az[H_DIM], g_bz[H_DIM], g_ah[H_DIM], g_bh[H_DIM];  // raw gate coeffs
__device__ float g_coef[DEG_C * H_DIM];     // monomial coeffs of g_k(t), t = a/A_FIT
__device__ float g_probs[P_DIM];

// ---------------- deg atomics (4 edges/thread) + gate-fold (merged grid) ----------------
// blocks [0, DEG_BLOCKS) : degree accumulation
// block DEG_BLOCKS       : fold z-gate (az, bz)   [raw, no prescale]
// block DEG_BLOCKS + 1   : fold h-gate (ah, bh)
__global__ void __launch_bounds__(256) k_deg_fold(
        const int* __restrict__ ei,    const float* __restrict__ ew,
        const float* __restrict__ cwz, const float* __restrict__ cbz,
        const float* __restrict__ Wz,  const float* __restrict__ lbz,
        const float* __restrict__ cwh, const float* __restrict__ cbh,
        const float* __restrict__ Wh,  const float* __restrict__ lbh) {
    int b = blockIdx.x;
    int tid = threadIdx.x;
    if (b < DEG_BLOCKS) {
        int e4 = (b * 256 + tid) * 4;
        int4   d = *(const int4*)  (ei + E_EDGES + e4);
        float4 w = *(const float4*)(ew + e4);
        atomicAdd(&g_deg[d.x], w.x);
        atomicAdd(&g_deg[d.y], w.y);
        atomicAdd(&g_deg[d.z], w.z);
        atomicAdd(&g_deg[d.w], w.w);
        return;
    }
    // fold: 256 threads = (k in [0,128)) x (half in {0,1}); each covers 64 h-rows.
    bool zgate = (b == DEG_BLOCKS);
    const float* cw = zgate ? cwz : cwh;
    const float* cb = zgate ? cbz : cbh;
    const float* W  = zgate ? Wz  : Wh;
    const float* lb = zgate ? lbz : lbh;
    float* ga = zgate ? g_az : g_ah;
    float* gb = zgate ? g_bz : g_bh;

    int k    = tid & 127;
    int half = tid >> 7;
    float pa = 0.f, pb = 0.f;
#pragma unroll 8
    for (int i = 0; i < 64; i++) {
        int h = half * 64 + i;
        float w = W[h * H_DIM + k];
        pa = fmaf(cw[h], w, pa);
        pb = fmaf(cb[h], w, pb);
    }
    __shared__ float sa[H_DIM], sb[H_DIM];
    if (half == 1) { sa[k] = pa; sb[k] = pb; }
    __syncthreads();
    if (half == 0) {
        ga[k] = pa + sa[k];
        gb[k] = pb + sb[k] + lb[k];
    }
}

// ---------------- dinv(+deg reset) + xs prescale + softmax + Chebyshev fit ----------------
// blocks [0, DINV_BLOCKS) : dinv + prescale (+softmax b0/t0)
// block DINV_BLOCKS       : per-k degree-9 Chebyshev fit of
//                           g_k(a) = (0.5 - 0.5*tanh(0.5*(az*a+bz))) * tanh(ah*a+bh)
__global__ void __launch_bounds__(256) k_dinv(const float* __restrict__ x,
                                              const float* __restrict__ att) {
    int tid = threadIdx.x;
    if (blockIdx.x == DINV_BLOCKS) {
        if (tid >= H_DIM) return;
        int k = tid;
        float azf = g_az[k], bzf = g_bz[k], ahf = g_ah[k], bhf = g_bh[k];
        float c[DEG_C];
#pragma unroll
        for (int m = 0; m < DEG_C; m++) c[m] = 0.f;
        for (int i = 0; i < M_FIT; i++) {
            float xx = cospif((2 * i + 1) / (2.0f * M_FIT));
            float a  = A_FIT * xx;
            float gz = 0.5f - 0.5f * tanhf(0.5f * fmaf(azf, a, bzf));
            float gh = tanhf(fmaf(ahf, a, bhf));
            float g  = gz * gh;
            float T0 = 1.0f, T1 = xx;
            c[0] += g;
            c[1] += g * xx;
#pragma unroll
            for (int m = 2; m < DEG_C; m++) {
                float T = 2.0f * xx * T1 - T0;
                c[m] += g * T;
                T0 = T1; T1 = T;
            }
        }
        c[0] *= 1.0f / M_FIT;
#pragma unroll
        for (int m = 1; m < DEG_C; m++) c[m] *= 2.0f / M_FIT;
        // Chebyshev -> monomial
        float mono[DEG_C], Tp[DEG_C], Tc[DEG_C];
#pragma unroll
        for (int j = 0; j < DEG_C; j++) { Tp[j] = 0.f; Tc[j] = 0.f; }
        Tp[0] = 1.0f; Tc[1] = 1.0f;
#pragma unroll
        for (int j = 0; j < DEG_C; j++) mono[j] = c[0] * Tp[j] + c[1] * Tc[j];
#pragma unroll
        for (int m = 2; m < DEG_C; m++) {
            float Tn[DEG_C];
            Tn[0] = -Tp[0];
#pragma unroll
            for (int j = 1; j < DEG_C; j++) Tn[j] = 2.0f * Tc[j - 1] - Tp[j];
#pragma unroll
            for (int j = 0; j < DEG_C; j++) mono[j] += c[m] * Tn[j];
#pragma unroll
            for (int j = 0; j < DEG_C; j++) { Tp[j] = Tc[j]; Tc[j] = Tn[j]; }
        }
#pragma unroll
        for (int j = 0; j < DEG_C; j++) g_coef[j * H_DIM + k] = mono[j];
        return;
    }
    __shared__ float s_dinv[256];
    int n0 = blockIdx.x * 256;
    int n  = n0 + tid;
    float dv = 0.0f;
    if (n < N_NODES) {
        float d = g_deg[n] + 1.0f;       // self-loop weight folded here
        dv = rsqrtf(d);                  // d >= 1 > 0 always
        g_dinv[n] = dv;
        g_deg[n]  = 0.0f;                // reset for next launch (replay-safe)
    }
    s_dinv[tid] = dv;
    __syncthreads();
    int base  = n0 * P_DIM;
    int count = min(256, N_NODES - n0) * P_DIM;
    for (int j = tid; j < count; j += 256) {
        g_xs[base + j] = s_dinv[j / P_DIM] * x[base + j];
    }
    if (blockIdx.x == 0 && tid == 0) {
        float m = -1e30f;
        for (int p = 0; p < P_DIM; p++) m = fmaxf(m, att[p]);
        float ex[P_DIM]; float s = 0.f;
        for (int p = 0; p < P_DIM; p++) { ex[p] = __expf(att[p] - m); s += ex[p]; }
        float inv = 1.0f / s;
        for (int p = 0; p < P_DIM; p++) g_probs[p] = ex[p] * inv;
    }
}

// ---------------- edge scatter: 3 lanes per edge -> min sector count ----------------
__device__ __forceinline__ void red_add_v4(float* addr, float4 v) {
    asm volatile("red.global.add.v4.f32 [%0], {%1, %2, %3, %4};"
                 :: "l"(addr), "f"(v.x), "f"(v.y), "f"(v.z), "f"(v.w)
                 : "memory");
}

__global__ void __launch_bounds__(256) k_edge(const int* __restrict__ ei,
                                              const float* __restrict__ ew) {
    int warp_g = (blockIdx.x * blockDim.x + threadIdx.x) >> 5;
    int lane   = threadIdx.x & 31;
    if (lane >= 3 * EDGES_PER_WARP) return;          // 2 idle lanes per warp
    int el = lane / 3;                                // edge-in-warp 0..9
    int j  = lane - el * 3;                           // quarter index 0..2
    int e  = warp_g * EDGES_PER_WARP + el;
    if (e >= E_EDGES) return;
    int   s = __ldg(ei + e);
    int   d = __ldg(ei + E_EDGES + e);
    float w = __ldg(ew + e);
    float4 v = *(const float4*)(g_xs + (size_t)s * P_DIM + 4 * j);
    v.x *= w; v.y *= w; v.z *= w; v.w *= w;
    red_add_v4(g_agg + (size_t)d * P_DIM + 4 * j, v);
}

// ---------------- node kernel: cooperative moments, 16 nodes/block -----------------------
__global__ void __launch_bounds__(256) k_node(const float* __restrict__ wout,
                                              const float* __restrict__ bout,
                                              float* __restrict__ out) {
    __shared__ float s_woutT[O_DIM * H_DIM];           // [o][k]
    __shared__ float s_coef [DEG_C * H_DIM];           // [j][k]
    __shared__ float s_pw   [NB * DEG_C * P_DIM];      // [i][j][p]
    __shared__ float s_m    [NB * DEG_C];              // [i][j]
    __shared__ float s_bout [O_DIM];

    int tid = threadIdx.x;
    int n0  = blockIdx.x * NB;

    // staging (overlaps phase 0)
    for (int i = tid; i < H_DIM * O_DIM; i += 256) {
        int k = i / O_DIM, o = i - k * O_DIM;
        s_woutT[o * H_DIM + k] = wout[i];              // transpose -> conflict-free LDS
    }
    for (int i = tid; i < DEG_C * H_DIM; i += 256) s_coef[i] = g_coef[i];
    if (tid < O_DIM) s_bout[tid] = bout[tid];

    // phase 0: thread (i, p) computes w_p * t^j power vector (t = clamp(a/A))
    if (tid < NB * P_DIM) {                            // 192 threads
        int i = tid / P_DIM;
        int p = tid - i * P_DIM;
        int g = n0 * P_DIM + tid;                      // fully coalesced
        float dv = g_dinv[n0 + i];
        float aa = dv * (g_agg[g] + g_xs[g]);
        g_agg[g] = 0.0f;                               // reset for next launch
        float t  = fminf(fmaxf(aa * (1.0f / A_FIT), -1.0f), 1.0f);
        float pw = g_probs[p];
        float* dst = s_pw + (i * DEG_C) * P_DIM + p;
#pragma unroll
        for (int j = 0; j < DEG_C; j++) {
            dst[j * P_DIM] = pw;
            pw *= t;
        }
    }
    __syncthreads();

    // phase 1: thread (i, j) sums 12 periods -> moment m[i][j]
    if (tid < NB * DEG_C) {                            // 160 threads
        const float* src = s_pw + tid * P_DIM;
        float m = 0.f;
#pragma unroll
        for (int p = 0; p < P_DIM; p++) m += src[p];
        s_m[tid] = m;
    }
    __syncthreads();

    // phase 2: each warp handles 2 nodes (k-parallel epilogue)
    int warp = tid >> 5, lane = tid & 31;
#pragma unroll
    for (int u = 0; u < 2; u++) {
        int i = warp * 2 + u;
        int n = n0 + i;

        float m[DEG_C];
#pragma unroll
        for (int j = 0; j < DEG_C; j++) m[j] = s_m[i * DEG_C + j];   // broadcast LDS

        float hacc[4] = {0.f, 0.f, 0.f, 0.f};
#pragma unroll
        for (int j = 0; j < DEG_C; j++) {
#pragma unroll
            for (int q = 0; q < 4; q++)
                hacc[q] = fmaf(m[j], s_coef[j * H_DIM + lane + 32 * q], hacc[q]);
        }

        // elu + out matvec (O=12)
        float o_acc[O_DIM];
#pragma unroll
        for (int o = 0; o < O_DIM; o++) o_acc[o] = 0.f;
#pragma unroll
        for (int q = 0; q < 4; q++) {
            float hk = hacc[q];
            hk = (hk > 0.f) ? hk : (__expf(hk) - 1.0f);
            int k = lane + 32 * q;
#pragma unroll
            for (int o = 0; o < O_DIM; o++)
                o_acc[o] = fmaf(hk, s_woutT[o * H_DIM + k], o_acc[o]);
        }

        // split-ownership butterfly: 18 SHFLs
        float v6[6];
        bool lo16 = (lane & 16) == 0;
#pragma unroll
        for (int t = 0; t < 6; t++) {
            float send = lo16 ? o_acc[t + 6] : o_acc[t];
            float recv = __shfl_xor_sync(0xffffffffu, send, 16);
            v6[t] = (lo16 ? o_acc[t] : o_acc[t + 6]) + recv;
        }
        float v3[3];
        bool lo8 = (lane & 8) == 0;
#pragma unroll
        for (int t = 0; t < 3; t++) {
            float send = lo8 ? v6[t + 3] : v6[t];
            float recv = __shfl_xor_sync(0xffffffffu, send, 8);
            v3[t] = (lo8 ? v6[t] : v6[t + 3]) + recv;
        }
#pragma unroll
        for (int off = 4; off > 0; off >>= 1) {
#pragma unroll
            for (int t = 0; t < 3; t++)
                v3[t] += __shfl_xor_sync(0xffffffffu, v3[t], off);
        }
        int r = lane & 7;
        if (r < 3) {
            int o = 3 * (lane >> 3) + r;
            out[(size_t)n * O_DIM + o] = v3[r] + s_bout[o];
        }
    }
}

// ---------------- launch ----------------
extern "C" void kernel_launch(void* const* d_in, const int* in_sizes, int n_in,
                              void* d_out, int out_size) {
    const float* x    = (const float*)d_in[0];
    const int*   ei   = (const int*)  d_in[1];
    const float* ew   = (const float*)d_in[2];
    const float* att  = (const float*)d_in[3];
    const float* cwz  = (const float*)d_in[4];
    const float* cbz  = (const float*)d_in[5];
    const float* Wz   = (const float*)d_in[6];
    const float* lbz  = (const float*)d_in[7];
    // r-gate inputs (d_in[8..11]) are mathematically dead: H=0 => R unused
    const float* cwh  = (const float*)d_in[12];
    const float* cbh  = (const float*)d_in[13];
    const float* Wh   = (const float*)d_in[14];
    const float* lbh  = (const float*)d_in[15];
    const float* wout = (const float*)d_in[16];
    const float* bout = (const float*)d_in[17];
    float* out = (float*)d_out;

    k_deg_fold<<<DEG_BLOCKS + 2, 256>>>(ei, ew, cwz, cbz, Wz, lbz,
                                        cwh, cbh, Wh, lbh);
    k_dinv<<<DINV_BLOCKS + 1, 256>>>(x, att);
    int edge_warps  = (E_EDGES + EDGES_PER_WARP - 1) / EDGES_PER_WARP;   // 64000
    int edge_blocks = (edge_warps + 7) / 8;                               // 8000
    k_edge<<<edge_blocks, 256>>>(ei, ew);
    k_node<<<N_NODES / NB, 256>>>(wout, bout, out);
}